// round 5
// baseline (speedup 1.0000x reference)
#include <cuda_runtime.h>
#include <cuda_bf16.h>
#include <math.h>

// ---------------- problem constants ----------------
#define EMBED_DIM 1280
#define NUM_HEADS 16
#define HEAD_DIM 80
#define ROT_DIM 40
#define NUM_SEQS 8
#define SEQ_LEN 2048
#define TOTAL (NUM_SEQS * SEQ_LEN)      // 16384
#define QKV_N (3 * EMBED_DIM)           // 3840

// ---------------- scratch (no cudaMalloc allowed) ----------------
__device__ float g_qkv[(size_t)TOTAL * QKV_N];     // 251.6 MB
__device__ float g_attn[(size_t)TOTAL * EMBED_DIM]; // 83.9 MB

// ---------------- SGEMM: C = A(MxK) * B(KxN) + bias, row-major ----------------
// BM=BN=128, BK=8, 256 threads, 8x8 microtile split as 2x(4) halves.
#define BM 128
#define BN 128
#define BK 8

__global__ __launch_bounds__(256, 2) void sgemm_bias(
    const float* __restrict__ A, const float* __restrict__ B,
    const float* __restrict__ bias, float* __restrict__ C,
    int M, int N, int K)
{
    __shared__ float As[BK][BM];
    __shared__ float Bs[BK][BN];

    const int bx = blockIdx.x;   // N tile
    const int by = blockIdx.y;   // M tile
    const int tid = threadIdx.x;
    const int tx = tid & 15;     // 0..15
    const int ty = tid >> 4;     // 0..15

    // A tile loaders: 128 rows x 8 cols = 1024 floats = 256 float4
    const int aRow = tid >> 1;          // 0..127
    const int aCol = (tid & 1) * 4;     // 0 or 4
    // B tile loaders: 8 rows x 128 cols
    const int bRow = tid >> 5;          // 0..7
    const int bCol = (tid & 31) * 4;    // 0..124

    const float* Aptr = A + (size_t)(by * BM) * K;
    const float* Bptr = B + bx * BN;

    float acc[8][8];
#pragma unroll
    for (int i = 0; i < 8; i++)
#pragma unroll
        for (int j = 0; j < 8; j++) acc[i][j] = 0.f;

    for (int k0 = 0; k0 < K; k0 += BK) {
        float4 av = *(const float4*)(Aptr + (size_t)aRow * K + k0 + aCol);
        As[aCol + 0][aRow] = av.x;
        As[aCol + 1][aRow] = av.y;
        As[aCol + 2][aRow] = av.z;
        As[aCol + 3][aRow] = av.w;
        float4 bv = *(const float4*)(Bptr + (size_t)(k0 + bRow) * N + bCol);
        *(float4*)&Bs[bRow][bCol] = bv;
        __syncthreads();

#pragma unroll
        for (int kk = 0; kk < BK; kk++) {
            float4 a0 = *(const float4*)&As[kk][ty * 4];
            float4 a1 = *(const float4*)&As[kk][ty * 4 + 64];
            float4 b0 = *(const float4*)&Bs[kk][tx * 4];
            float4 b1 = *(const float4*)&Bs[kk][tx * 4 + 64];
            float a[8] = {a0.x, a0.y, a0.z, a0.w, a1.x, a1.y, a1.z, a1.w};
            float b[8] = {b0.x, b0.y, b0.z, b0.w, b1.x, b1.y, b1.z, b1.w};
#pragma unroll
            for (int i = 0; i < 8; i++)
#pragma unroll
                for (int j = 0; j < 8; j++) acc[i][j] = fmaf(a[i], b[j], acc[i][j]);
        }
        __syncthreads();
    }

    const int row0 = by * BM;
    const int col0 = bx * BN;
    float4 bias0 = *(const float4*)(bias + col0 + tx * 4);
    float4 bias1 = *(const float4*)(bias + col0 + tx * 4 + 64);
    float bb[8] = {bias0.x, bias0.y, bias0.z, bias0.w, bias1.x, bias1.y, bias1.z, bias1.w};

#pragma unroll
    for (int i = 0; i < 8; i++) {
        int r = row0 + ty * 4 + (i < 4 ? i : 64 + (i - 4));
#pragma unroll
        for (int jj = 0; jj < 2; jj++) {
            int c = col0 + tx * 4 + jj * 64;
            float4 v;
            v.x = acc[i][jj * 4 + 0] + bb[jj * 4 + 0];
            v.y = acc[i][jj * 4 + 1] + bb[jj * 4 + 1];
            v.z = acc[i][jj * 4 + 2] + bb[jj * 4 + 2];
            v.w = acc[i][jj * 4 + 3] + bb[jj * 4 + 3];
            *(float4*)(C + (size_t)r * N + c) = v;
        }
    }
}

// ---------------- RoPE (in place on q,k parts of qkv) ----------------
__global__ void rope_kernel(float* __restrict__ qkv,
                            const float* __restrict__ cosp,
                            const float* __restrict__ sinp)
{
    int idx = blockIdx.x * blockDim.x + threadIdx.x;
    const int n = TOTAL * NUM_HEADS * ROT_DIM;
    if (idx >= n) return;
    int d = idx % ROT_DIM;
    int h = (idx / ROT_DIM) % NUM_HEADS;
    int t = idx / (ROT_DIM * NUM_HEADS);
    float c = cosp[t * ROT_DIM + d];
    float s = sinp[t * ROT_DIM + d];
    float* base = qkv + (size_t)t * QKV_N;
#pragma unroll
    for (int part = 0; part < 2; part++) {
        float* p = base + part * EMBED_DIM + h * HEAD_DIM;
        float x1 = p[d];
        float x2 = p[d + ROT_DIM];
        p[d]           = x1 * c - x2 * s;
        p[d + ROT_DIM] = x2 * c + x1 * s;
    }
}

// ---------------- Flash attention (fp32, online softmax) ----------------
// Block: 128 threads = 128 query rows. Grid: (qblocks=16, heads=16, seqs=8).
// K/V tiles of 32 keys in smem (broadcast reads). O[80], s[32] in registers.
#define AQ 128
#define AKT 32
#define AD 80
#define QPAD 81
#define ATTN_SMEM ((AQ * QPAD + 2 * AKT * AD) * 4)

__global__ __launch_bounds__(128, 3) void attn_kernel(
    const float* __restrict__ qkv, float* __restrict__ out)
{
    extern __shared__ float sm[];
    float* Qs = sm;                    // AQ * QPAD
    float* Ks = Qs + AQ * QPAD;        // AKT * AD
    float* Vs = Ks + AKT * AD;         // AKT * AD

    const int qb = blockIdx.x;
    const int h  = blockIdx.y;
    const int sq = blockIdx.z;
    const int tid = threadIdx.x;

    const int tok0 = sq * SEQ_LEN;
    const int q0 = tok0 + qb * AQ;
    const float scale = 0.11180339887498948f; // 1/sqrt(80)

    // load Q block (scaled) into smem
    for (int i = tid; i < AQ * 20; i += 128) {
        int r = i / 20;
        int c4 = (i % 20) * 4;
        float4 v = *(const float4*)(qkv + (size_t)(q0 + r) * QKV_N + h * HEAD_DIM + c4);
        float* dst = &Qs[r * QPAD + c4];
        dst[0] = v.x * scale; dst[1] = v.y * scale;
        dst[2] = v.z * scale; dst[3] = v.w * scale;
    }

    float O[AD];
#pragma unroll
    for (int d = 0; d < AD; d++) O[d] = 0.f;
    float m = -1e30f, l = 0.f;

    const float* qrow = &Qs[tid * QPAD];

    for (int kt = 0; kt < SEQ_LEN / AKT; kt++) {
        __syncthreads();
        const int k0 = tok0 + kt * AKT;
        for (int i = tid; i < AKT * 20; i += 128) {
            int r = i / 20;
            int c4 = (i % 20) * 4;
            const float* src = qkv + (size_t)(k0 + r) * QKV_N + h * HEAD_DIM + c4;
            *(float4*)&Ks[r * AD + c4] = *(const float4*)(src + EMBED_DIM);
            *(float4*)&Vs[r * AD + c4] = *(const float4*)(src + 2 * EMBED_DIM);
        }
        __syncthreads();

        float s[AKT];
#pragma unroll
        for (int j = 0; j < AKT; j++) s[j] = 0.f;

        for (int c4 = 0; c4 < 20; c4++) {  // rolled to bound I-footprint
            float qx = qrow[c4 * 4 + 0];
            float qy = qrow[c4 * 4 + 1];
            float qz = qrow[c4 * 4 + 2];
            float qw = qrow[c4 * 4 + 3];
#pragma unroll
            for (int j = 0; j < AKT; j++) {
                float4 kv = *(const float4*)&Ks[j * AD + c4 * 4];
                s[j] = fmaf(qx, kv.x, s[j]);
                s[j] = fmaf(qy, kv.y, s[j]);
                s[j] = fmaf(qz, kv.z, s[j]);
                s[j] = fmaf(qw, kv.w, s[j]);
            }
        }

        float mt = m;
#pragma unroll
        for (int j = 0; j < AKT; j++) mt = fmaxf(mt, s[j]);
        float alpha = __expf(m - mt);
        m = mt;
        float psum = 0.f;
#pragma unroll
        for (int j = 0; j < AKT; j++) {
            s[j] = __expf(s[j] - mt);
            psum += s[j];
        }
        l = l * alpha + psum;
#pragma unroll
        for (int d = 0; d < AD; d++) O[d] *= alpha;

#pragma unroll
        for (int j = 0; j < AKT; j++) {
            float p = s[j];
#pragma unroll
            for (int c4 = 0; c4 < 20; c4++) {
                float4 vv = *(const float4*)&Vs[j * AD + c4 * 4];
                O[c4 * 4 + 0] = fmaf(p, vv.x, O[c4 * 4 + 0]);
                O[c4 * 4 + 1] = fmaf(p, vv.y, O[c4 * 4 + 1]);
                O[c4 * 4 + 2] = fmaf(p, vv.z, O[c4 * 4 + 2]);
                O[c4 * 4 + 3] = fmaf(p, vv.w, O[c4 * 4 + 3]);
            }
        }
    }

    float inv = 1.f / l;
    float* optr = out + (size_t)(q0 + tid) * EMBED_DIM + h * HEAD_DIM;
#pragma unroll
    for (int c4 = 0; c4 < 20; c4++) {
        float4 v;
        v.x = O[c4 * 4 + 0] * inv;
        v.y = O[c4 * 4 + 1] * inv;
        v.z = O[c4 * 4 + 2] * inv;
        v.w = O[c4 * 4 + 3] * inv;
        *(float4*)(optr + c4 * 4) = v;
    }
}

// ---------------- launch ----------------
extern "C" void kernel_launch(void* const* d_in, const int* in_sizes, int n_in,
                              void* d_out, int out_size)
{
    const float* x    = (const float*)d_in[0];
    // d_in[1] = cu_seqlens (layout is fixed/uniform; unused)
    const float* cosp = (const float*)d_in[2];
    const float* sinp = (const float*)d_in[3];
    const float* Wqkv = (const float*)d_in[4];
    const float* bqkv = (const float*)d_in[5];
    const float* Wout = (const float*)d_in[6];
    const float* bout = (const float*)d_in[7];
    float* out = (float*)d_out;

    float* qkv = nullptr;
    float* attn = nullptr;
    cudaGetSymbolAddress((void**)&qkv, g_qkv);
    cudaGetSymbolAddress((void**)&attn, g_attn);

    // 1) QKV GEMM + bias
    sgemm_bias<<<dim3(QKV_N / BN, TOTAL / BM), 256>>>(x, Wqkv, bqkv, qkv,
                                                      TOTAL, QKV_N, EMBED_DIM);
    // 2) RoPE in place on q,k
    {
        int n = TOTAL * NUM_HEADS * ROT_DIM;
        rope_kernel<<<(n + 255) / 256, 256>>>(qkv, cosp, sinp);
    }
    // 3) Flash attention
    cudaFuncSetAttribute(attn_kernel, cudaFuncAttributeMaxDynamicSharedMemorySize,
                         ATTN_SMEM);
    attn_kernel<<<dim3(SEQ_LEN / AQ, NUM_HEADS, NUM_SEQS), 128, ATTN_SMEM>>>(qkv, attn);
    // 4) Output projection + bias
    sgemm_bias<<<dim3(EMBED_DIM / BN, TOTAL / BM), 256>>>(attn, Wout, bout, out,
                                                          TOTAL, EMBED_DIM, EMBED_DIM);
}

// round 11
// speedup vs baseline: 1.0065x; 1.0065x over previous
#include <cuda_runtime.h>
#include <cuda_bf16.h>
#include <math.h>

// ---------------- problem constants ----------------
#define EMBED_DIM 1280
#define NUM_HEADS 16
#define HEAD_DIM 80
#define ROT_DIM 40
#define NUM_SEQS 8
#define SEQ_LEN 2048
#define TOTAL (NUM_SEQS * SEQ_LEN)      // 16384
#define QKV_N (3 * EMBED_DIM)           // 3840

// ---------------- scratch (no cudaMalloc allowed) ----------------
__device__ float g_qkv[(size_t)TOTAL * QKV_N];      // 251.6 MB
__device__ float g_attn[(size_t)TOTAL * EMBED_DIM]; // 83.9 MB

// ---------------- packed fp32x2 helpers (Blackwell dual-fp32 pipe) ----------------
typedef unsigned long long u64;

__device__ __forceinline__ u64 bcast2(float v) {
    u64 r;
    asm("mov.b64 %0, {%1, %1};" : "=l"(r) : "r"(__float_as_uint(v)));
    return r;
}
__device__ __forceinline__ void unpack2(u64 p, float& lo, float& hi) {
    unsigned int a, b;
    asm("mov.b64 {%0, %1}, %2;" : "=r"(a), "=r"(b) : "l"(p));
    lo = __uint_as_float(a);
    hi = __uint_as_float(b);
}
__device__ __forceinline__ u64 fma2(u64 a, u64 b, u64 c) {
    u64 d;
    asm("fma.rn.f32x2 %0, %1, %2, %3;" : "=l"(d) : "l"(a), "l"(b), "l"(c));
    return d;
}
__device__ __forceinline__ u64 mul2(u64 a, u64 b) {
    u64 d;
    asm("mul.rn.f32x2 %0, %1, %2;" : "=l"(d) : "l"(a), "l"(b));
    return d;
}

// ---------------- SGEMM: C = A(MxK) * B(KxN) + bias, row-major ----------------
// BM=BN=128, BK=8, 256 threads, 8x8 microtile computed as 4 row-pairs x 8 cols
// of packed f32x2 FMAs.
#define BM 128
#define BN 128
#define BK 8

__global__ __launch_bounds__(256, 2) void sgemm_bias(
    const float* __restrict__ A, const float* __restrict__ B,
    const float* __restrict__ bias, float* __restrict__ C,
    int M, int N, int K)
{
    __shared__ __align__(16) float As[BK][BM];
    __shared__ __align__(16) float Bs[BK][BN];

    const int bx = blockIdx.x;   // N tile
    const int by = blockIdx.y;   // M tile
    const int tid = threadIdx.x;
    const int tx = tid & 15;     // 0..15
    const int ty = tid >> 4;     // 0..15

    const int aRow = tid >> 1;          // 0..127
    const int aCol = (tid & 1) * 4;     // 0 or 4
    const int bRow = tid >> 5;          // 0..7
    const int bCol = (tid & 31) * 4;    // 0..124

    const float* Aptr = A + (size_t)(by * BM) * K;
    const float* Bptr = B + bx * BN;

    // acc2[p][j]: row-pair p (packed lo/hi = 2 consecutive M rows), col j
    u64 acc2[4][8];
#pragma unroll
    for (int p = 0; p < 4; p++)
#pragma unroll
        for (int j = 0; j < 8; j++) acc2[p][j] = 0ull;

    for (int k0 = 0; k0 < K; k0 += BK) {
        float4 av = *(const float4*)(Aptr + (size_t)aRow * K + k0 + aCol);
        As[aCol + 0][aRow] = av.x;
        As[aCol + 1][aRow] = av.y;
        As[aCol + 2][aRow] = av.z;
        As[aCol + 3][aRow] = av.w;
        float4 bv = *(const float4*)(Bptr + (size_t)(k0 + bRow) * N + bCol);
        *(float4*)&Bs[bRow][bCol] = bv;
        __syncthreads();

#pragma unroll
        for (int kk = 0; kk < BK; kk++) {
            // a row-pairs: free packing from contiguous smem (rows m, m+1)
            ulonglong2 a0 = *(const ulonglong2*)&As[kk][ty * 4];
            ulonglong2 a1 = *(const ulonglong2*)&As[kk][ty * 4 + 64];
            float4 b0f = *(const float4*)&Bs[kk][tx * 4];
            float4 b1f = *(const float4*)&Bs[kk][tx * 4 + 64];
            u64 ap[4] = {a0.x, a0.y, a1.x, a1.y};
            u64 bb[8];
            bb[0] = bcast2(b0f.x); bb[1] = bcast2(b0f.y);
            bb[2] = bcast2(b0f.z); bb[3] = bcast2(b0f.w);
            bb[4] = bcast2(b1f.x); bb[5] = bcast2(b1f.y);
            bb[6] = bcast2(b1f.z); bb[7] = bcast2(b1f.w);
#pragma unroll
            for (int p = 0; p < 4; p++)
#pragma unroll
                for (int j = 0; j < 8; j++)
                    acc2[p][j] = fma2(ap[p], bb[j], acc2[p][j]);
        }
        __syncthreads();
    }

    const int row0 = by * BM;
    const int col0 = bx * BN;
    float4 bias0 = *(const float4*)(bias + col0 + tx * 4);
    float4 bias1 = *(const float4*)(bias + col0 + tx * 4 + 64);
    float bbv[8] = {bias0.x, bias0.y, bias0.z, bias0.w,
                    bias1.x, bias1.y, bias1.z, bias1.w};

#pragma unroll
    for (int p = 0; p < 4; p++) {
        // pair p covers rows: ty*4 + (p&1)*2 + (p>>1)*64 , +1
        int rbase = row0 + ty * 4 + (p & 1) * 2 + (p >> 1) * 64;
        float lo[8], hi[8];
#pragma unroll
        for (int j = 0; j < 8; j++) unpack2(acc2[p][j], lo[j], hi[j]);
#pragma unroll
        for (int half = 0; half < 2; half++) {
            int r = rbase + half;
            const float* src = half ? hi : lo;
            float4 v0, v1;
            v0.x = src[0] + bbv[0]; v0.y = src[1] + bbv[1];
            v0.z = src[2] + bbv[2]; v0.w = src[3] + bbv[3];
            v1.x = src[4] + bbv[4]; v1.y = src[5] + bbv[5];
            v1.z = src[6] + bbv[6]; v1.w = src[7] + bbv[7];
            *(float4*)(C + (size_t)r * N + col0 + tx * 4) = v0;
            *(float4*)(C + (size_t)r * N + col0 + tx * 4 + 64) = v1;
        }
    }
}

// ---------------- RoPE (in place on q,k parts of qkv) ----------------
__global__ void rope_kernel(float* __restrict__ qkv,
                            const float* __restrict__ cosp,
                            const float* __restrict__ sinp)
{
    int idx = blockIdx.x * blockDim.x + threadIdx.x;
    const int n = TOTAL * NUM_HEADS * ROT_DIM;
    if (idx >= n) return;
    int d = idx % ROT_DIM;
    int h = (idx / ROT_DIM) % NUM_HEADS;
    int t = idx / (ROT_DIM * NUM_HEADS);
    float c = cosp[t * ROT_DIM + d];
    float s = sinp[t * ROT_DIM + d];
    float* base = qkv + (size_t)t * QKV_N;
#pragma unroll
    for (int part = 0; part < 2; part++) {
        float* p = base + part * EMBED_DIM + h * HEAD_DIM;
        float x1 = p[d];
        float x2 = p[d + ROT_DIM];
        p[d]           = x1 * c - x2 * s;
        p[d + ROT_DIM] = x2 * c + x1 * s;
    }
}

// ---------------- Flash attention (fp32x2, online softmax) ----------------
// Block: 128 threads = 128 query rows. Grid: (qblocks=16, heads=16, seqs=8).
// K stored TRANSPOSED in smem (Kt[d][j], j contiguous) so score pairs pack
// into f32x2 lanes; V stays [j][d] so O pairs pack over d.
// QPAD=84: row stride 336B -> 16B-aligned float4 reads per tid; 84 mod 32 = 20
// keeps the 8-lane LDS.128 phases on distinct banks (0,20,8,28,16,4,24,12).
#define AQ 128
#define AKT 32
#define AD 80
#define QPAD 84
#define ATTN_SMEM ((AQ * QPAD + AD * AKT + AKT * AD) * 4)

__global__ __launch_bounds__(128, 3) void attn_kernel(
    const float* __restrict__ qkv, float* __restrict__ out)
{
    extern __shared__ __align__(16) float sm[];
    float* Qs = sm;                    // AQ * QPAD
    float* Kt = Qs + AQ * QPAD;        // AD * AKT  (transposed: [d][j])
    float* Vs = Kt + AD * AKT;         // AKT * AD

    const int qb = blockIdx.x;
    const int h  = blockIdx.y;
    const int sq = blockIdx.z;
    const int tid = threadIdx.x;

    const int tok0 = sq * SEQ_LEN;
    const int q0 = tok0 + qb * AQ;
    const float scale = 0.11180339887498948f; // 1/sqrt(80)

    // load Q block (scaled) into smem
    for (int i = tid; i < AQ * 20; i += 128) {
        int r = i / 20;
        int c4 = (i % 20) * 4;
        float4 v = *(const float4*)(qkv + (size_t)(q0 + r) * QKV_N + h * HEAD_DIM + c4);
        float* dst = &Qs[r * QPAD + c4];
        dst[0] = v.x * scale; dst[1] = v.y * scale;
        dst[2] = v.z * scale; dst[3] = v.w * scale;
    }

    u64 O2[40];
#pragma unroll
    for (int p = 0; p < 40; p++) O2[p] = 0ull;
    float m = -1e30f, l = 0.f;

    const float* qrow = &Qs[tid * QPAD];

    for (int kt = 0; kt < SEQ_LEN / AKT; kt++) {
        __syncthreads();
        const int k0 = tok0 + kt * AKT;
        // K: transposed store, conflict-free STS (j = lane across banks).
        // Gmem read is column-strided (accepted: L2-resident tile).
        for (int i = tid; i < AKT * 20; i += 128) {
            int j  = i & 31;
            int d4 = i >> 5;
            float4 v = *(const float4*)(qkv + (size_t)(k0 + j) * QKV_N +
                                        h * HEAD_DIM + 4 * d4 + EMBED_DIM);
            Kt[(4 * d4 + 0) * AKT + j] = v.x;
            Kt[(4 * d4 + 1) * AKT + j] = v.y;
            Kt[(4 * d4 + 2) * AKT + j] = v.z;
            Kt[(4 * d4 + 3) * AKT + j] = v.w;
        }
        // V: coalesced, row-major [j][d]
        for (int i = tid; i < AKT * 20; i += 128) {
            int r = i / 20;
            int c4 = (i % 20) * 4;
            *(float4*)&Vs[r * AD + c4] =
                *(const float4*)(qkv + (size_t)(k0 + r) * QKV_N +
                                 h * HEAD_DIM + c4 + 2 * EMBED_DIM);
        }
        __syncthreads();

        // ---- scores: s2[16] packed pairs over j ----
        u64 s2[16];
#pragma unroll
        for (int p = 0; p < 16; p++) s2[p] = 0ull;

        for (int d4 = 0; d4 < 20; d4++) {  // rolled to bound I-footprint
            float4 q4 = *(const float4*)&qrow[d4 * 4];
            float qv[4] = {q4.x, q4.y, q4.z, q4.w};
#pragma unroll
            for (int dd = 0; dd < 4; dd++) {
                u64 qb2 = bcast2(qv[dd]);
                const float* krow = &Kt[(d4 * 4 + dd) * AKT];
#pragma unroll
                for (int jq = 0; jq < 8; jq++) {
                    ulonglong2 k2 = *(const ulonglong2*)(krow + jq * 4);
                    s2[jq * 2]     = fma2(qb2, k2.x, s2[jq * 2]);
                    s2[jq * 2 + 1] = fma2(qb2, k2.y, s2[jq * 2 + 1]);
                }
            }
        }

        float s[AKT];
#pragma unroll
        for (int jq = 0; jq < 8; jq++) {
            unpack2(s2[jq * 2],     s[jq * 4 + 0], s[jq * 4 + 1]);
            unpack2(s2[jq * 2 + 1], s[jq * 4 + 2], s[jq * 4 + 3]);
        }

        float mt = m;
#pragma unroll
        for (int j = 0; j < AKT; j++) mt = fmaxf(mt, s[j]);
        float alpha = __expf(m - mt);
        m = mt;
        float psum = 0.f;
#pragma unroll
        for (int j = 0; j < AKT; j++) {
            s[j] = __expf(s[j] - mt);
            psum += s[j];
        }
        l = l * alpha + psum;

        u64 ab = bcast2(alpha);
#pragma unroll
        for (int p = 0; p < 40; p++) O2[p] = mul2(O2[p], ab);

        for (int j = 0; j < AKT; j++) {
            u64 pb = bcast2(s[j]);
            const float* vrow = &Vs[j * AD];
#pragma unroll
            for (int c4 = 0; c4 < 20; c4++) {
                ulonglong2 v2 = *(const ulonglong2*)(vrow + c4 * 4);
                O2[2 * c4]     = fma2(pb, v2.x, O2[2 * c4]);
                O2[2 * c4 + 1] = fma2(pb, v2.y, O2[2 * c4 + 1]);
            }
        }
    }

    float inv = 1.f / l;
    float* optr = out + (size_t)(q0 + tid) * EMBED_DIM + h * HEAD_DIM;
#pragma unroll
    for (int c4 = 0; c4 < 20; c4++) {
        float o0, o1, o2, o3;
        unpack2(O2[2 * c4],     o0, o1);
        unpack2(O2[2 * c4 + 1], o2, o3);
        float4 v;
        v.x = o0 * inv; v.y = o1 * inv;
        v.z = o2 * inv; v.w = o3 * inv;
        *(float4*)(optr + c4 * 4) = v;
    }
}

// ---------------- launch ----------------
extern "C" void kernel_launch(void* const* d_in, const int* in_sizes, int n_in,
                              void* d_out, int out_size)
{
    const float* x    = (const float*)d_in[0];
    // d_in[1] = cu_seqlens (layout is fixed/uniform; unused)
    const float* cosp = (const float*)d_in[2];
    const float* sinp = (const float*)d_in[3];
    const float* Wqkv = (const float*)d_in[4];
    const float* bqkv = (const float*)d_in[5];
    const float* Wout = (const float*)d_in[6];
    const float* bout = (const float*)d_in[7];
    float* out = (float*)d_out;

    float* qkv = nullptr;
    float* attn = nullptr;
    cudaGetSymbolAddress((void**)&qkv, g_qkv);
    cudaGetSymbolAddress((void**)&attn, g_attn);

    // 1) QKV GEMM + bias
    sgemm_bias<<<dim3(QKV_N / BN, TOTAL / BM), 256>>>(x, Wqkv, bqkv, qkv,
                                                      TOTAL, QKV_N, EMBED_DIM);
    // 2) RoPE in place on q,k
    {
        int n = TOTAL * NUM_HEADS * ROT_DIM;
        rope_kernel<<<(n + 255) / 256, 256>>>(qkv, cosp, sinp);
    }
    // 3) Flash attention
    cudaFuncSetAttribute(attn_kernel, cudaFuncAttributeMaxDynamicSharedMemorySize,
                         ATTN_SMEM);
    attn_kernel<<<dim3(SEQ_LEN / AQ, NUM_HEADS, NUM_SEQS), 128, ATTN_SMEM>>>(qkv, attn);
    // 4) Output projection + bias
    sgemm_bias<<<dim3(EMBED_DIM / BN, TOTAL / BM), 256>>>(attn, Wout, bout, out,
                                                          TOTAL, EMBED_DIM, EMBED_DIM);
}

// round 16
// speedup vs baseline: 1.3536x; 1.3448x over previous
#include <cuda_runtime.h>
#include <cuda_bf16.h>
#include <math.h>
#include <stdint.h>

// ---------------- problem constants ----------------
#define EMBED_DIM 1280
#define NUM_HEADS 16
#define HEAD_DIM 80
#define ROT_DIM 40
#define NUM_SEQS 8
#define SEQ_LEN 2048
#define TOTAL (NUM_SEQS * SEQ_LEN)      // 16384
#define QKV_N (3 * EMBED_DIM)           // 3840

// ---------------- scratch (no cudaMalloc allowed) ----------------
__device__ float g_qkv[(size_t)TOTAL * QKV_N];      // 251.6 MB
__device__ float g_attn[(size_t)TOTAL * EMBED_DIM]; // 83.9 MB
// bf16 hi/lo splits (reused: x then attn-out; Wqkv then Wout)
__device__ __nv_bfloat16 g_ahi[(size_t)TOTAL * EMBED_DIM];
__device__ __nv_bfloat16 g_alo[(size_t)TOTAL * EMBED_DIM];
__device__ __nv_bfloat16 g_bhi[(size_t)EMBED_DIM * QKV_N];
__device__ __nv_bfloat16 g_blo[(size_t)EMBED_DIM * QKV_N];

// ---------------- packed fp32x2 helpers (kept for attention) ----------------
typedef unsigned long long u64;

__device__ __forceinline__ u64 bcast2(float v) {
    u64 r;
    asm("mov.b64 %0, {%1, %1};" : "=l"(r) : "r"(__float_as_uint(v)));
    return r;
}
__device__ __forceinline__ void unpack2(u64 p, float& lo, float& hi) {
    unsigned int a, b;
    asm("mov.b64 {%0, %1}, %2;" : "=r"(a), "=r"(b) : "l"(p));
    lo = __uint_as_float(a);
    hi = __uint_as_float(b);
}
__device__ __forceinline__ u64 fma2(u64 a, u64 b, u64 c) {
    u64 d;
    asm("fma.rn.f32x2 %0, %1, %2, %3;" : "=l"(d) : "l"(a), "l"(b), "l"(c));
    return d;
}
__device__ __forceinline__ u64 mul2(u64 a, u64 b) {
    u64 d;
    asm("mul.rn.f32x2 %0, %1, %2;" : "=l"(d) : "l"(a), "l"(b));
    return d;
}

// ---------------- fp32 -> (bf16 hi, bf16 lo) split ----------------
__device__ __forceinline__ uint32_t pack_bf2(__nv_bfloat16 a, __nv_bfloat16 b) {
    __nv_bfloat162 t = __halves2bfloat162(a, b);
    return *reinterpret_cast<uint32_t*>(&t);
}

__global__ void split_kernel(const float* __restrict__ in,
                             __nv_bfloat16* __restrict__ hi,
                             __nv_bfloat16* __restrict__ lo, int n4)
{
    int i = blockIdx.x * blockDim.x + threadIdx.x;
    if (i >= n4) return;
    float4 v = reinterpret_cast<const float4*>(in)[i];
    float f[4] = {v.x, v.y, v.z, v.w};
    __nv_bfloat16 h[4], l[4];
#pragma unroll
    for (int j = 0; j < 4; j++) {
        h[j] = __float2bfloat16_rn(f[j]);
        l[j] = __float2bfloat16_rn(f[j] - __bfloat162float(h[j]));
    }
    uint2 hv = make_uint2(pack_bf2(h[0], h[1]), pack_bf2(h[2], h[3]));
    uint2 lv = make_uint2(pack_bf2(l[0], l[1]), pack_bf2(l[2], l[3]));
    reinterpret_cast<uint2*>(hi)[i] = hv;
    reinterpret_cast<uint2*>(lo)[i] = lv;
}

// ---------------- tensor-core GEMM: C = A*B + bias (3x bf16 split) ----------------
// A: MxK row-major (hi/lo bf16), B: KxN row-major (hi/lo bf16), C fp32.
// Block tile 128x128x32, 8 warps, warp tile 64x32 (4 m16 x 4 n8 mma tiles).
#define GBM 128
#define GBN 128
#define GBK 32
#define APAD 40   // bf16 per A smem row (32 + 8) -> 80B stride, conflict-free
#define BPAD 136  // bf16 per B smem row (128 + 8) -> 272B stride, conflict-free

__device__ __forceinline__ void ldsm_x4(uint32_t* r, const __nv_bfloat16* p) {
    uint32_t a = (uint32_t)__cvta_generic_to_shared(p);
    asm volatile("ldmatrix.sync.aligned.m8n8.x4.shared.b16 {%0,%1,%2,%3}, [%4];"
                 : "=r"(r[0]), "=r"(r[1]), "=r"(r[2]), "=r"(r[3]) : "r"(a));
}
__device__ __forceinline__ void ldsm_x4_t(uint32_t* r, const __nv_bfloat16* p) {
    uint32_t a = (uint32_t)__cvta_generic_to_shared(p);
    asm volatile("ldmatrix.sync.aligned.m8n8.x4.trans.shared.b16 {%0,%1,%2,%3}, [%4];"
                 : "=r"(r[0]), "=r"(r[1]), "=r"(r[2]), "=r"(r[3]) : "r"(a));
}
__device__ __forceinline__ void mma_bf16(float* c, const uint32_t* a, const uint32_t* b) {
    asm volatile(
        "mma.sync.aligned.m16n8k16.row.col.f32.bf16.bf16.f32 "
        "{%0,%1,%2,%3}, {%4,%5,%6,%7}, {%8,%9}, {%0,%1,%2,%3};"
        : "+f"(c[0]), "+f"(c[1]), "+f"(c[2]), "+f"(c[3])
        : "r"(a[0]), "r"(a[1]), "r"(a[2]), "r"(a[3]), "r"(b[0]), "r"(b[1]));
}

__global__ __launch_bounds__(256, 2) void gemm_bf16x3(
    const __nv_bfloat16* __restrict__ Ahi, const __nv_bfloat16* __restrict__ Alo,
    const __nv_bfloat16* __restrict__ Bhi, const __nv_bfloat16* __restrict__ Blo,
    const float* __restrict__ bias, float* __restrict__ C,
    int M, int N, int K)
{
    __shared__ __align__(16) __nv_bfloat16 sAhi[GBM * APAD];
    __shared__ __align__(16) __nv_bfloat16 sAlo[GBM * APAD];
    __shared__ __align__(16) __nv_bfloat16 sBhi[GBK * BPAD];
    __shared__ __align__(16) __nv_bfloat16 sBlo[GBK * BPAD];

    const int tid = threadIdx.x;
    const int lane = tid & 31;
    const int wid = tid >> 5;
    const int warp_m = wid >> 2;       // 0..1 -> m offset *64
    const int warp_n = wid & 3;        // 0..3 -> n offset *32
    const int bx = blockIdx.x;         // N tile
    const int by = blockIdx.y;         // M tile

    float acc[4][4][4];
#pragma unroll
    for (int mt = 0; mt < 4; mt++)
#pragma unroll
        for (int nt = 0; nt < 4; nt++)
#pragma unroll
            for (int i = 0; i < 4; i++) acc[mt][nt][i] = 0.f;

    const __nv_bfloat16* Abase_h = Ahi + (size_t)(by * GBM) * K;
    const __nv_bfloat16* Abase_l = Alo + (size_t)(by * GBM) * K;
    const __nv_bfloat16* Bbase_h = Bhi + bx * GBN;
    const __nv_bfloat16* Bbase_l = Blo + bx * GBN;

    // fragment addresses (per-lane, loop-invariant)
    const int a_row = warp_m * 64 + (lane & 15);
    const int a_col = (lane >> 4) * 8;
    const int b_row = (lane & 7) + ((lane >> 3) & 1) * 8;
    const int b_coln = warp_n * 32 + (lane >> 4) * 8;

    for (int kt = 0; kt < K / GBK; kt++) {
        // ---- load A tile: 128x32 bf16 (hi+lo), 8 bf16 (16B) per chunk ----
#pragma unroll
        for (int i = 0; i < 2; i++) {
            int gi = tid + i * 256;          // 0..511
            int r = gi >> 2;                 // 0..127
            int kc = (gi & 3) * 8;           // 0,8,16,24
            const size_t go = (size_t)r * K + kt * GBK + kc;
            *(uint4*)&sAhi[r * APAD + kc] = *(const uint4*)(Abase_h + go);
            *(uint4*)&sAlo[r * APAD + kc] = *(const uint4*)(Abase_l + go);
        }
        // ---- load B tile: 32x128 bf16 (hi+lo) ----
#pragma unroll
        for (int i = 0; i < 2; i++) {
            int gi = tid + i * 256;          // 0..511
            int r = gi >> 4;                 // 0..31
            int nc = (gi & 15) * 8;          // 0..120
            const size_t go = (size_t)(kt * GBK + r) * N + nc;
            *(uint4*)&sBhi[r * BPAD + nc] = *(const uint4*)(Bbase_h + go);
            *(uint4*)&sBlo[r * BPAD + nc] = *(const uint4*)(Bbase_l + go);
        }
        __syncthreads();

#pragma unroll
        for (int s = 0; s < 2; s++) {
            const int kb = s * 16;
            // B fragments: 2 n16 groups x (hi,lo)
            uint32_t bh[8], bl[8];
            ldsm_x4_t(&bh[0], &sBhi[(kb + b_row) * BPAD + b_coln]);
            ldsm_x4_t(&bh[4], &sBhi[(kb + b_row) * BPAD + b_coln + 16]);
            ldsm_x4_t(&bl[0], &sBlo[(kb + b_row) * BPAD + b_coln]);
            ldsm_x4_t(&bl[4], &sBlo[(kb + b_row) * BPAD + b_coln + 16]);

#pragma unroll
            for (int mt = 0; mt < 4; mt++) {
                uint32_t ah[4], al[4];
                ldsm_x4(ah, &sAhi[(a_row + mt * 16) * APAD + kb + a_col]);
                ldsm_x4(al, &sAlo[(a_row + mt * 16) * APAD + kb + a_col]);
#pragma unroll
                for (int nt = 0; nt < 4; nt++) {
                    const uint32_t* bhp = &bh[(nt >> 1) * 4 + (nt & 1) * 2];
                    const uint32_t* blp = &bl[(nt >> 1) * 4 + (nt & 1) * 2];
                    mma_bf16(acc[mt][nt], ah, bhp);  // hi*hi
                    mma_bf16(acc[mt][nt], ah, blp);  // hi*lo
                    mma_bf16(acc[mt][nt], al, bhp);  // lo*hi
                }
            }
        }
        __syncthreads();
    }

    // ---- epilogue: fragment -> gmem with bias ----
    const int row_base = by * GBM + warp_m * 64;
    const int col_base = bx * GBN + warp_n * 32;
#pragma unroll
    for (int nt = 0; nt < 4; nt++) {
        int c0 = col_base + nt * 8 + (lane & 3) * 2;
        float2 bv = *(const float2*)(bias + c0);
#pragma unroll
        for (int mt = 0; mt < 4; mt++) {
            int r0 = row_base + mt * 16 + (lane >> 2);
            float2 v0 = make_float2(acc[mt][nt][0] + bv.x, acc[mt][nt][1] + bv.y);
            float2 v1 = make_float2(acc[mt][nt][2] + bv.x, acc[mt][nt][3] + bv.y);
            *(float2*)(C + (size_t)r0 * N + c0) = v0;
            *(float2*)(C + (size_t)(r0 + 8) * N + c0) = v1;
        }
    }
}

// ---------------- RoPE (in place on q,k parts of qkv) ----------------
__global__ void rope_kernel(float* __restrict__ qkv,
                            const float* __restrict__ cosp,
                            const float* __restrict__ sinp)
{
    int idx = blockIdx.x * blockDim.x + threadIdx.x;
    const int n = TOTAL * NUM_HEADS * ROT_DIM;
    if (idx >= n) return;
    int d = idx % ROT_DIM;
    int h = (idx / ROT_DIM) % NUM_HEADS;
    int t = idx / (ROT_DIM * NUM_HEADS);
    float c = cosp[t * ROT_DIM + d];
    float s = sinp[t * ROT_DIM + d];
    float* base = qkv + (size_t)t * QKV_N;
#pragma unroll
    for (int part = 0; part < 2; part++) {
        float* p = base + part * EMBED_DIM + h * HEAD_DIM;
        float x1 = p[d];
        float x2 = p[d + ROT_DIM];
        p[d]           = x1 * c - x2 * s;
        p[d + ROT_DIM] = x2 * c + x1 * s;
    }
}

// ---------------- Flash attention (fp32x2, online softmax) ----------------
#define AQ 128
#define AKT 32
#define AD 80
#define QPAD 84
#define ATTN_SMEM ((AQ * QPAD + AD * AKT + AKT * AD) * 4)

__global__ __launch_bounds__(128, 3) void attn_kernel(
    const float* __restrict__ qkv, float* __restrict__ out)
{
    extern __shared__ __align__(16) float sm[];
    float* Qs = sm;                    // AQ * QPAD
    float* Kt = Qs + AQ * QPAD;        // AD * AKT  (transposed: [d][j])
    float* Vs = Kt + AD * AKT;         // AKT * AD

    const int qb = blockIdx.x;
    const int h  = blockIdx.y;
    const int sq = blockIdx.z;
    const int tid = threadIdx.x;

    const int tok0 = sq * SEQ_LEN;
    const int q0 = tok0 + qb * AQ;
    const float scale = 0.11180339887498948f; // 1/sqrt(80)

    for (int i = tid; i < AQ * 20; i += 128) {
        int r = i / 20;
        int c4 = (i % 20) * 4;
        float4 v = *(const float4*)(qkv + (size_t)(q0 + r) * QKV_N + h * HEAD_DIM + c4);
        float* dst = &Qs[r * QPAD + c4];
        dst[0] = v.x * scale; dst[1] = v.y * scale;
        dst[2] = v.z * scale; dst[3] = v.w * scale;
    }

    u64 O2[40];
#pragma unroll
    for (int p = 0; p < 40; p++) O2[p] = 0ull;
    float m = -1e30f, l = 0.f;

    const float* qrow = &Qs[tid * QPAD];

    for (int kt = 0; kt < SEQ_LEN / AKT; kt++) {
        __syncthreads();
        const int k0 = tok0 + kt * AKT;
        for (int i = tid; i < AKT * 20; i += 128) {
            int j  = i & 31;
            int d4 = i >> 5;
            float4 v = *(const float4*)(qkv + (size_t)(k0 + j) * QKV_N +
                                        h * HEAD_DIM + 4 * d4 + EMBED_DIM);
            Kt[(4 * d4 + 0) * AKT + j] = v.x;
            Kt[(4 * d4 + 1) * AKT + j] = v.y;
            Kt[(4 * d4 + 2) * AKT + j] = v.z;
            Kt[(4 * d4 + 3) * AKT + j] = v.w;
        }
        for (int i = tid; i < AKT * 20; i += 128) {
            int r = i / 20;
            int c4 = (i % 20) * 4;
            *(float4*)&Vs[r * AD + c4] =
                *(const float4*)(qkv + (size_t)(k0 + r) * QKV_N +
                                 h * HEAD_DIM + c4 + 2 * EMBED_DIM);
        }
        __syncthreads();

        u64 s2[16];
#pragma unroll
        for (int p = 0; p < 16; p++) s2[p] = 0ull;

        for (int d4 = 0; d4 < 20; d4++) {
            float4 q4 = *(const float4*)&qrow[d4 * 4];
            float qv[4] = {q4.x, q4.y, q4.z, q4.w};
#pragma unroll
            for (int dd = 0; dd < 4; dd++) {
                u64 qb2 = bcast2(qv[dd]);
                const float* krow = &Kt[(d4 * 4 + dd) * AKT];
#pragma unroll
                for (int jq = 0; jq < 8; jq++) {
                    ulonglong2 k2 = *(const ulonglong2*)(krow + jq * 4);
                    s2[jq * 2]     = fma2(qb2, k2.x, s2[jq * 2]);
                    s2[jq * 2 + 1] = fma2(qb2, k2.y, s2[jq * 2 + 1]);
                }
            }
        }

        float s[AKT];
#pragma unroll
        for (int jq = 0; jq < 8; jq++) {
            unpack2(s2[jq * 2],     s[jq * 4 + 0], s[jq * 4 + 1]);
            unpack2(s2[jq * 2 + 1], s[jq * 4 + 2], s[jq * 4 + 3]);
        }

        float mt = m;
#pragma unroll
        for (int j = 0; j < AKT; j++) mt = fmaxf(mt, s[j]);
        float alpha = __expf(m - mt);
        m = mt;
        float psum = 0.f;
#pragma unroll
        for (int j = 0; j < AKT; j++) {
            s[j] = __expf(s[j] - mt);
            psum += s[j];
        }
        l = l * alpha + psum;

        u64 ab = bcast2(alpha);
#pragma unroll
        for (int p = 0; p < 40; p++) O2[p] = mul2(O2[p], ab);

        for (int j = 0; j < AKT; j++) {
            u64 pb = bcast2(s[j]);
            const float* vrow = &Vs[j * AD];
#pragma unroll
            for (int c4 = 0; c4 < 20; c4++) {
                ulonglong2 v2 = *(const ulonglong2*)(vrow + c4 * 4);
                O2[2 * c4]     = fma2(pb, v2.x, O2[2 * c4]);
                O2[2 * c4 + 1] = fma2(pb, v2.y, O2[2 * c4 + 1]);
            }
        }
    }

    float inv = 1.f / l;
    float* optr = out + (size_t)(q0 + tid) * EMBED_DIM + h * HEAD_DIM;
#pragma unroll
    for (int c4 = 0; c4 < 20; c4++) {
        float o0, o1, o2, o3;
        unpack2(O2[2 * c4],     o0, o1);
        unpack2(O2[2 * c4 + 1], o2, o3);
        float4 v;
        v.x = o0 * inv; v.y = o1 * inv;
        v.z = o2 * inv; v.w = o3 * inv;
        *(float4*)(optr + c4 * 4) = v;
    }
}

// ---------------- launch ----------------
extern "C" void kernel_launch(void* const* d_in, const int* in_sizes, int n_in,
                              void* d_out, int out_size)
{
    const float* x    = (const float*)d_in[0];
    // d_in[1] = cu_seqlens (layout fixed/uniform; unused)
    const float* cosp = (const float*)d_in[2];
    const float* sinp = (const float*)d_in[3];
    const float* Wqkv = (const float*)d_in[4];
    const float* bqkv = (const float*)d_in[5];
    const float* Wout = (const float*)d_in[6];
    const float* bout = (const float*)d_in[7];
    float* out = (float*)d_out;

    float* qkv = nullptr;
    float* attn = nullptr;
    __nv_bfloat16 *ahi, *alo, *bhi, *blo;
    cudaGetSymbolAddress((void**)&qkv, g_qkv);
    cudaGetSymbolAddress((void**)&attn, g_attn);
    cudaGetSymbolAddress((void**)&ahi, g_ahi);
    cudaGetSymbolAddress((void**)&alo, g_alo);
    cudaGetSymbolAddress((void**)&bhi, g_bhi);
    cudaGetSymbolAddress((void**)&blo, g_blo);

    // 1) split x and Wqkv to bf16 hi/lo
    {
        int n4 = TOTAL * EMBED_DIM / 4;
        split_kernel<<<(n4 + 255) / 256, 256>>>(x, ahi, alo, n4);
        int w4 = EMBED_DIM * QKV_N / 4;
        split_kernel<<<(w4 + 255) / 256, 256>>>(Wqkv, bhi, blo, w4);
    }
    // 2) QKV GEMM + bias (tensor cores, 3x bf16)
    gemm_bf16x3<<<dim3(QKV_N / GBN, TOTAL / GBM), 256>>>(
        ahi, alo, bhi, blo, bqkv, qkv, TOTAL, QKV_N, EMBED_DIM);
    // 3) RoPE in place on q,k
    {
        int n = TOTAL * NUM_HEADS * ROT_DIM;
        rope_kernel<<<(n + 255) / 256, 256>>>(qkv, cosp, sinp);
    }
    // 4) Flash attention
    cudaFuncSetAttribute(attn_kernel, cudaFuncAttributeMaxDynamicSharedMemorySize,
                         ATTN_SMEM);
    attn_kernel<<<dim3(SEQ_LEN / AQ, NUM_HEADS, NUM_SEQS), 128, ATTN_SMEM>>>(qkv, attn);
    // 5) split attn output and Wout (reuse buffers)
    {
        int n4 = TOTAL * EMBED_DIM / 4;
        split_kernel<<<(n4 + 255) / 256, 256>>>(attn, ahi, alo, n4);
        int w4 = EMBED_DIM * EMBED_DIM / 4;
        split_kernel<<<(w4 + 255) / 256, 256>>>(Wout, bhi, blo, w4);
    }
    // 6) Output projection + bias (tensor cores)
    gemm_bf16x3<<<dim3(EMBED_DIM / GBN, TOTAL / GBM), 256>>>(
        ahi, alo, bhi, blo, bout, out, TOTAL, EMBED_DIM, EMBED_DIM);
}